// round 6
// baseline (speedup 1.0000x reference)
#include <cuda_runtime.h>
#include <cstdint>

#define MAX_NODES 65536

// Scratch (allocation-free: __device__ globals)
__device__ float  g_M[2 * 256];     // folded matrix M[r][k] = sum_i W2a[r][i] * W1[i][k]
__device__ float  g_c[2];           // folded bias c[r] = W2a[r]@W1b + W2b_bias[r]
__device__ float2 g_pu[MAX_NODES];  // per-node src contribution (2 classes)
__device__ float2 g_pv[MAX_NODES];  // per-node dst contribution

// ---------------------------------------------------------------------------
// Kernel 1: fold W2a @ W1 -> M [2 x 256], and c = W2a @ W1b + b2. One CTA.
//   W1w: [256, 256] row-major (out, in). W2w: [2, 288] row-major. W2b: [2].
// ---------------------------------------------------------------------------
__global__ void k_fold(const float* __restrict__ W1w, const float* __restrict__ W1b,
                       const float* __restrict__ W2w, const float* __restrict__ W2b)
{
    const int t = threadIdx.x;          // 512 threads
    const int r = t >> 8;               // class 0/1
    const int k = t & 255;              // input column of W1
    float acc = 0.0f;
    #pragma unroll 8
    for (int i = 0; i < 256; i++)
        acc = fmaf(W2w[r * 288 + i], W1w[i * 256 + k], acc);   // coalesced over k
    g_M[r * 256 + k] = acc;

    if (t < 2) {
        float c = W2b[t];
        #pragma unroll 8
        for (int i = 0; i < 256; i++)
            c = fmaf(W2w[t * 288 + i], W1b[i], c);
        g_c[t] = c;
    }
}

// ---------------------------------------------------------------------------
// Kernel 2: per-node transform. pu[n] = h[n] @ M[:, :128]^T, pv[n] = h[n] @ M[:, 128:]^T
//   One thread per node; M staged in shared (broadcast reads, conflict-free).
// ---------------------------------------------------------------------------
__global__ void __launch_bounds__(256)
k_node(const float* __restrict__ h, int n_nodes)
{
    __shared__ float4 sMu0[32], sMv0[32], sMu1[32], sMv1[32];
    const int t = threadIdx.x;
    if (t < 32) {
        const float4* gm = (const float4*)g_M;
        sMu0[t] = gm[t];        // M[0][  0..127]
        sMv0[t] = gm[32 + t];   // M[0][128..255]
        sMu1[t] = gm[64 + t];   // M[1][  0..127]
        sMv1[t] = gm[96 + t];   // M[1][128..255]
    }
    __syncthreads();

    const int n = blockIdx.x * 256 + t;
    if (n >= n_nodes) return;

    const float4* __restrict__ hv = (const float4*)(h + (size_t)n * 128);
    float pu0 = 0.f, pu1 = 0.f, pv0 = 0.f, pv1 = 0.f;
    #pragma unroll
    for (int q = 0; q < 32; q++) {
        const float4 x = hv[q];
        const float4 a = sMu0[q], b = sMv0[q], cc = sMu1[q], d = sMv1[q];
        pu0 = fmaf(x.x, a.x, pu0);  pu0 = fmaf(x.y, a.y, pu0);
        pu0 = fmaf(x.z, a.z, pu0);  pu0 = fmaf(x.w, a.w, pu0);
        pv0 = fmaf(x.x, b.x, pv0);  pv0 = fmaf(x.y, b.y, pv0);
        pv0 = fmaf(x.z, b.z, pv0);  pv0 = fmaf(x.w, b.w, pv0);
        pu1 = fmaf(x.x, cc.x, pu1); pu1 = fmaf(x.y, cc.y, pu1);
        pu1 = fmaf(x.z, cc.z, pu1); pu1 = fmaf(x.w, cc.w, pu1);
        pv1 = fmaf(x.x, d.x, pv1);  pv1 = fmaf(x.y, d.y, pv1);
        pv1 = fmaf(x.z, d.z, pv1);  pv1 = fmaf(x.w, d.w, pv1);
    }
    g_pu[n] = make_float2(pu0, pu1);
    g_pv[n] = make_float2(pv0, pv1);
}

// ---------------------------------------------------------------------------
// Kernel 3: edge stage. 4 threads per edge (perfectly coalesced e reads):
//   out[edge] = pu[src] + pv[dst] + W2b @ e[edge] + c
// ---------------------------------------------------------------------------
__global__ void __launch_bounds__(256)
k_edge(const int* __restrict__ src, const int* __restrict__ dst,
       const float* __restrict__ e, const float* __restrict__ W2w,
       float2* __restrict__ out, int n_edges)
{
    const int t    = threadIdx.x;
    const int sub  = t & 3;                 // quarter of the 32-dim e row
    const int eloc = t >> 2;                // 0..63 edges per CTA
    const int edge = blockIdx.x * 64 + eloc;

    // per-thread W2b slice: rows {0,1}, columns 256 + sub*8 .. +8 (L1 broadcast)
    float w0[8], w1[8];
    #pragma unroll
    for (int q = 0; q < 8; q++) {
        w0[q] = W2w[256 + sub * 8 + q];
        w1[q] = W2w[288 + 256 + sub * 8 + q];
    }

    float s0 = 0.f, s1 = 0.f;
    if (edge < n_edges) {
        const float4* __restrict__ ep = (const float4*)(e + (size_t)edge * 32 + sub * 8);
        const float4 v0 = ep[0];
        const float4 v1 = ep[1];
        s0 = fmaf(w0[0], v0.x, s0); s1 = fmaf(w1[0], v0.x, s1);
        s0 = fmaf(w0[1], v0.y, s0); s1 = fmaf(w1[1], v0.y, s1);
        s0 = fmaf(w0[2], v0.z, s0); s1 = fmaf(w1[2], v0.z, s1);
        s0 = fmaf(w0[3], v0.w, s0); s1 = fmaf(w1[3], v0.w, s1);
        s0 = fmaf(w0[4], v1.x, s0); s1 = fmaf(w1[4], v1.x, s1);
        s0 = fmaf(w0[5], v1.y, s0); s1 = fmaf(w1[5], v1.y, s1);
        s0 = fmaf(w0[6], v1.z, s0); s1 = fmaf(w1[6], v1.z, s1);
        s0 = fmaf(w0[7], v1.w, s0); s1 = fmaf(w1[7], v1.w, s1);
    }
    // reduce the 4 sub-lanes of each edge
    s0 += __shfl_xor_sync(0xFFFFFFFFu, s0, 1);
    s1 += __shfl_xor_sync(0xFFFFFFFFu, s1, 1);
    s0 += __shfl_xor_sync(0xFFFFFFFFu, s0, 2);
    s1 += __shfl_xor_sync(0xFFFFFFFFu, s1, 2);

    if (sub == 0 && edge < n_edges) {
        const int su = src[edge];
        const int dv = dst[edge];
        const float2 a = g_pu[su];      // 400 KB table: L2-resident gather
        const float2 b = g_pv[dv];
        out[edge] = make_float2(s0 + a.x + b.x + g_c[0],
                                s1 + a.y + b.y + g_c[1]);
    }
}

// ---------------------------------------------------------------------------
extern "C" void kernel_launch(void* const* d_in, const int* in_sizes, int n_in,
                              void* d_out, int out_size)
{
    const float* h   = (const float*)d_in[0];
    const int*   src = (const int*)d_in[1];
    const int*   dst = (const int*)d_in[2];
    const float* e   = (const float*)d_in[3];
    const float* W1w = (const float*)d_in[4];
    const float* W1b = (const float*)d_in[5];
    const float* W2w = (const float*)d_in[6];
    const float* W2b = (const float*)d_in[7];
    float2* out = (float2*)d_out;

    const int n_nodes = in_sizes[0] / 128;
    const int n_edges = in_sizes[1];

    k_fold<<<1, 512>>>(W1w, W1b, W2w, W2b);
    k_node<<<(n_nodes + 255) / 256, 256>>>(h, n_nodes);
    k_edge<<<(n_edges + 63) / 64, 256>>>(src, dst, e, W2w, out, n_edges);
}

// round 8
// speedup vs baseline: 1.6100x; 1.6100x over previous
#include <cuda_runtime.h>
#include <cstdint>

#define MAX_NODES 65536

// Scratch (allocation-free: __device__ globals)
__device__ float  g_M[2 * 256];     // folded matrix M[r][k] = sum_i W2a[r][i] * W1[i][k]
__device__ float  g_c[2];           // folded bias c[r] = W2a[r]@W1b + b2[r]
__device__ float2 g_pu[MAX_NODES];  // per-node src contribution (2 classes)
__device__ float2 g_pv[MAX_NODES];  // per-node dst contribution

// ---------------------------------------------------------------------------
// Kernel 1: fold W2a @ W1 -> M [2 x 256], and c = W2a @ W1b + b2.
//   One warp per output element; lanes split K=256 (8 independent loads each),
//   then a 5-step shfl butterfly reduce. Deterministic, fully parallel.
//   Launch: 65 CTAs x 256 threads = 520 warps (514 used).
// ---------------------------------------------------------------------------
__global__ void __launch_bounds__(256)
k_fold(const float* __restrict__ W1w, const float* __restrict__ W1b,
       const float* __restrict__ W2w, const float* __restrict__ W2b)
{
    const int gw   = (blockIdx.x * blockDim.x + threadIdx.x) >> 5;  // global warp id
    const int lane = threadIdx.x & 31;

    if (gw < 512) {
        const int r = gw >> 8;          // class 0/1
        const int k = gw & 255;         // W1 input column
        float acc = 0.0f;
        #pragma unroll
        for (int j = 0; j < 8; j++) {
            const int i = j * 32 + lane;
            acc = fmaf(__ldg(&W2w[r * 288 + i]), __ldg(&W1w[i * 256 + k]), acc);
        }
        #pragma unroll
        for (int o = 16; o > 0; o >>= 1)
            acc += __shfl_xor_sync(0xFFFFFFFFu, acc, o);
        if (lane == 0) g_M[r * 256 + k] = acc;
    } else if (gw < 514) {
        const int r = gw - 512;
        float acc = 0.0f;
        #pragma unroll
        for (int j = 0; j < 8; j++) {
            const int i = j * 32 + lane;
            acc = fmaf(__ldg(&W2w[r * 288 + i]), __ldg(&W1b[i]), acc);
        }
        #pragma unroll
        for (int o = 16; o > 0; o >>= 1)
            acc += __shfl_xor_sync(0xFFFFFFFFu, acc, o);
        if (lane == 0) g_c[r] = acc + W2b[r];
    }
}

// ---------------------------------------------------------------------------
// Kernel 2: per-node transform. pu[n] = h[n] @ M[:, :128]^T, pv[n] = h[n] @ M[:, 128:]^T
//   One thread per node; M staged in shared (broadcast reads, conflict-free).
// ---------------------------------------------------------------------------
__global__ void __launch_bounds__(256)
k_node(const float* __restrict__ h, int n_nodes)
{
    __shared__ float4 sMu0[32], sMv0[32], sMu1[32], sMv1[32];
    const int t = threadIdx.x;
    if (t < 32) {
        const float4* gm = (const float4*)g_M;
        sMu0[t] = gm[t];        // M[0][  0..127]
        sMv0[t] = gm[32 + t];   // M[0][128..255]
        sMu1[t] = gm[64 + t];   // M[1][  0..127]
        sMv1[t] = gm[96 + t];   // M[1][128..255]
    }
    __syncthreads();

    const int n = blockIdx.x * 256 + t;
    if (n >= n_nodes) return;

    const float4* __restrict__ hv = (const float4*)(h + (size_t)n * 128);
    float pu0 = 0.f, pu1 = 0.f, pv0 = 0.f, pv1 = 0.f;
    #pragma unroll
    for (int q = 0; q < 32; q++) {
        const float4 x = hv[q];
        const float4 a = sMu0[q], b = sMv0[q], cc = sMu1[q], d = sMv1[q];
        pu0 = fmaf(x.x, a.x, pu0);  pu0 = fmaf(x.y, a.y, pu0);
        pu0 = fmaf(x.z, a.z, pu0);  pu0 = fmaf(x.w, a.w, pu0);
        pv0 = fmaf(x.x, b.x, pv0);  pv0 = fmaf(x.y, b.y, pv0);
        pv0 = fmaf(x.z, b.z, pv0);  pv0 = fmaf(x.w, b.w, pv0);
        pu1 = fmaf(x.x, cc.x, pu1); pu1 = fmaf(x.y, cc.y, pu1);
        pu1 = fmaf(x.z, cc.z, pu1); pu1 = fmaf(x.w, cc.w, pu1);
        pv1 = fmaf(x.x, d.x, pv1);  pv1 = fmaf(x.y, d.y, pv1);
        pv1 = fmaf(x.z, d.z, pv1);  pv1 = fmaf(x.w, d.w, pv1);
    }
    g_pu[n] = make_float2(pu0, pu1);
    g_pv[n] = make_float2(pv0, pv1);
}

// ---------------------------------------------------------------------------
// Kernel 3: edge stage. 4 threads per edge (perfectly coalesced e reads):
//   out[edge] = pu[src] + pv[dst] + W2b @ e[edge] + c
// ---------------------------------------------------------------------------
__global__ void __launch_bounds__(256)
k_edge(const int* __restrict__ src, const int* __restrict__ dst,
       const float* __restrict__ e, const float* __restrict__ W2w,
       float2* __restrict__ out, int n_edges)
{
    const int t    = threadIdx.x;
    const int sub  = t & 3;                 // quarter of the 32-dim e row
    const int eloc = t >> 2;                // 0..63 edges per CTA
    const int edge = blockIdx.x * 64 + eloc;

    // per-thread W2b slice: rows {0,1}, columns 256 + sub*8 .. +8 (L1 broadcast)
    float w0[8], w1[8];
    #pragma unroll
    for (int q = 0; q < 8; q++) {
        w0[q] = W2w[256 + sub * 8 + q];
        w1[q] = W2w[288 + 256 + sub * 8 + q];
    }

    float s0 = 0.f, s1 = 0.f;
    if (edge < n_edges) {
        const float4* __restrict__ ep = (const float4*)(e + (size_t)edge * 32 + sub * 8);
        const float4 v0 = ep[0];
        const float4 v1 = ep[1];
        s0 = fmaf(w0[0], v0.x, s0); s1 = fmaf(w1[0], v0.x, s1);
        s0 = fmaf(w0[1], v0.y, s0); s1 = fmaf(w1[1], v0.y, s1);
        s0 = fmaf(w0[2], v0.z, s0); s1 = fmaf(w1[2], v0.z, s1);
        s0 = fmaf(w0[3], v0.w, s0); s1 = fmaf(w1[3], v0.w, s1);
        s0 = fmaf(w0[4], v1.x, s0); s1 = fmaf(w1[4], v1.x, s1);
        s0 = fmaf(w0[5], v1.y, s0); s1 = fmaf(w1[5], v1.y, s1);
        s0 = fmaf(w0[6], v1.z, s0); s1 = fmaf(w1[6], v1.z, s1);
        s0 = fmaf(w0[7], v1.w, s0); s1 = fmaf(w1[7], v1.w, s1);
    }
    // reduce the 4 sub-lanes of each edge
    s0 += __shfl_xor_sync(0xFFFFFFFFu, s0, 1);
    s1 += __shfl_xor_sync(0xFFFFFFFFu, s1, 1);
    s0 += __shfl_xor_sync(0xFFFFFFFFu, s0, 2);
    s1 += __shfl_xor_sync(0xFFFFFFFFu, s1, 2);

    if (sub == 0 && edge < n_edges) {
        const int su = src[edge];
        const int dv = dst[edge];
        const float2 a = g_pu[su];      // 400 KB table: L2-resident gather
        const float2 b = g_pv[dv];
        out[edge] = make_float2(s0 + a.x + b.x + g_c[0],
                                s1 + a.y + b.y + g_c[1]);
    }
}

// ---------------------------------------------------------------------------
extern "C" void kernel_launch(void* const* d_in, const int* in_sizes, int n_in,
                              void* d_out, int out_size)
{
    const float* h   = (const float*)d_in[0];
    const int*   src = (const int*)d_in[1];
    const int*   dst = (const int*)d_in[2];
    const float* e   = (const float*)d_in[3];
    const float* W1w = (const float*)d_in[4];
    const float* W1b = (const float*)d_in[5];
    const float* W2w = (const float*)d_in[6];
    const float* W2b = (const float*)d_in[7];
    float2* out = (float2*)d_out;

    const int n_nodes = in_sizes[0] / 128;
    const int n_edges = in_sizes[1];

    k_fold<<<65, 256>>>(W1w, W1b, W2w, W2b);                // 514 warps, warp-per-output
    k_node<<<(n_nodes + 255) / 256, 256>>>(h, n_nodes);
    k_edge<<<(n_edges + 63) / 64, 256>>>(src, dst, e, W2w, out, n_edges);
}